// round 2
// baseline (speedup 1.0000x reference)
#include <cuda_runtime.h>
#include <cuda_bf16.h>
#include <math.h>

// Problem constants (hardcoded for this dataset: B=2, H=W=512)
#define B   2
#define H   512
#define W   512
#define HW  (H*W)            // 262144
#define PH  (H+1)            // pooled H = 513
#define PW  (W+1)            // pooled W = 513
#define PHW (PH*PW)          // 263169

// Scratch (static device memory; allocation APIs are forbidden)
__device__ float g_ang[(size_t)B * 8 * HW];       // (B,8,512,512)  16 MB
__device__ float g_pooled[(size_t)B * 8 * PHW];   // (B,8,513,513)  16.8 MB

__device__ __forceinline__ float fsqrt_fast(float x) {
    float r;
    asm("sqrt.approx.f32 %0, %1;" : "=f"(r) : "f"(x));
    return r;
}

// ----------------------------------------------------------------------------
// K1: spatial gradient (central diff /2, replicate pad) -> mag/ori -> 8-bin
//     soft angular histogram. Writes dense ang (only 2 of 8 channels nonzero).
// ----------------------------------------------------------------------------
__global__ __launch_bounds__(256)
void k_ang(const float* __restrict__ x) {
    const int j = blockIdx.x * 32 + threadIdx.x;
    const int i = blockIdx.y * 8  + threadIdx.y;
    const int b = blockIdx.z;

    const float* xb = x + (size_t)b * HW;
    const int jm = max(j - 1, 0),     jp = min(j + 1, W - 1);
    const int im = max(i - 1, 0),     ip = min(i + 1, H - 1);

    const float gx = 0.5f * (xb[i * W + jp] - xb[i * W + jm]);
    const float gy = 0.5f * (xb[ip * W + j] - xb[im * W + j]);

    const float mag = sqrtf(gx * gx + gy * gy + 1e-10f);
    const float TWO_PI = 6.283185307179586f;
    const float ori = atan2f(gy, gx + 1e-10f) + TWO_PI;   // (pi, 3pi]
    const float o   = ori * (8.0f / TWO_PI);              // (4, 12]
    const float bof = floorf(o);
    const float w1  = o - bof;                            // [0,1)
    const int b0 = ((int)bof) & 7;
    const int b1 = (b0 + 1) & 7;
    const float v0 = (1.0f - w1) * mag;
    const float v1 = w1 * mag;

    float* ap = g_ang + (size_t)b * 8 * HW + (size_t)i * W + j;
#pragma unroll
    for (int d = 0; d < 8; d++) {
        float v = (d == b0) ? v0 : ((d == b1) ? v1 : 0.0f);
        ap[(size_t)d * HW] = v;
    }
}

// ----------------------------------------------------------------------------
// K2: 4x4 triangular pooling (separable weights [.25,.75,.75,.25]^2), pad=2,
//     stride 1, zero padding. ang(512x512) -> pooled(513x513) per channel.
// ----------------------------------------------------------------------------
__global__ __launch_bounds__(256)
void k_pool() {
    const int q  = blockIdx.x * 32 + threadIdx.x;   // 0..512
    const int p  = blockIdx.y * 8  + threadIdx.y;   // 0..512
    const int bd = blockIdx.z;                      // 0..15  (b*8+d)
    if (p >= PH || q >= PW) return;

    const float* a = g_ang + (size_t)bd * HW;
    const float wv[4] = {0.25f, 0.75f, 0.75f, 0.25f};

    float acc = 0.0f;
#pragma unroll
    for (int ky = 0; ky < 4; ky++) {
        const int r = p - 2 + ky;
        if (r < 0 || r >= H) continue;
        float rowacc = 0.0f;
#pragma unroll
        for (int kx = 0; kx < 4; kx++) {
            const int c = q - 2 + kx;
            if (c < 0 || c >= W) continue;
            rowacc = fmaf(wv[kx], a[(size_t)r * W + c], rowacc);
        }
        acc = fmaf(wv[ky], rowacc, acc);
    }
    g_pooled[(size_t)bd * PHW + (size_t)p * PW + q] = acc;
}

// ----------------------------------------------------------------------------
// K3: fused neigh2channels gather + collapsed normalization chain.
//     out[b, d*16+y*4+x, i, j] = f( pooled[b,d,i-1+y,j-1+x] ) with
//     f(v) = sqrt( min(v, 0.2*||v||2) / S + 1e-10 ),  S = sum min(v, 0.2*||v||2)
//
//     Vectorized: each thread owns 4 consecutive j pixels. All SMEM reads are
//     LDS.128 (8-col row segment shared by the 4 pixels x 4 taps), all global
//     stores are STG.128 (warp writes 512B contiguous per channel).
// ----------------------------------------------------------------------------
#define TXV 32                  // threads in x
#define TYV 8                   // threads in y
#define PPT 4                   // pixels per thread along x
#define TILEX (TXV * PPT)       // 128 output cols per block
#define TROWS (TYV + 3)         // 11
#define TCOLS (TILEX + 3)       // 131 valid cols
#define TCOLSP 132              // padded to multiple of 4 (16B-aligned rows)

__global__ __launch_bounds__(256)
void k_final(float* __restrict__ out) {
    __shared__ float tile[8][TROWS][TCOLSP];   // 46464 B

    const int b  = blockIdx.z;
    const int j0 = blockIdx.x * TILEX;
    const int i0 = blockIdx.y * TYV;
    const int tx = threadIdx.x, ty = threadIdx.y;
    const int tid = ty * TXV + tx;

    // Load pooled tile: rows i0-1 .. i0+TYV+1, cols j0-1 .. j0+TILEX+1.
    // OOB (zero padding of the reshape conv) and the pad col -> 0.
    const float* pb = g_pooled + (size_t)b * 8 * PHW;
    const int NLOAD = 8 * TROWS * TCOLSP;
    for (int idx = tid; idx < NLOAD; idx += TXV * TYV) {
        const int d   = idx / (TROWS * TCOLSP);
        const int rem = idx % (TROWS * TCOLSP);
        const int r = rem / TCOLSP;
        const int c = rem % TCOLSP;
        const int pp = i0 - 1 + r;
        const int qq = j0 - 1 + c;
        float v = 0.0f;
        if (pp >= 0 && pp < PH && qq >= 0 && qq < PW && c < TCOLS)
            v = pb[(size_t)d * PHW + (size_t)pp * PW + qq];
        tile[d][r][c] = v;
    }
    __syncthreads();

    const int jl = tx * PPT;          // local col of pixel p=0 (tile col jl+p+xk)
    const int i  = i0 + ty;

    // Pass 1: per-pixel sum of squares over the 128-vector
    float sq[PPT] = {0.f, 0.f, 0.f, 0.f};
#pragma unroll
    for (int d = 0; d < 8; d++) {
#pragma unroll
        for (int y = 0; y < 4; y++) {
            const float4 A  = *(const float4*)&tile[d][ty + y][jl];
            const float4 Bv = *(const float4*)&tile[d][ty + y][jl + 4];
            const float v[8] = {A.x, A.y, A.z, A.w, Bv.x, Bv.y, Bv.z, Bv.w};
#pragma unroll
            for (int p = 0; p < PPT; p++) {
#pragma unroll
                for (int xk = 0; xk < 4; xk++) {
                    const float t = v[p + xk];
                    sq[p] = fmaf(t, t, sq[p]);
                }
            }
        }
    }

    float tclip[PPT];
#pragma unroll
    for (int p = 0; p < PPT; p++) tclip[p] = 0.2f * fsqrt_fast(sq[p]);

    // Pass 2: per-pixel clipped L1 sum
    float S[PPT] = {0.f, 0.f, 0.f, 0.f};
#pragma unroll
    for (int d = 0; d < 8; d++) {
#pragma unroll
        for (int y = 0; y < 4; y++) {
            const float4 A  = *(const float4*)&tile[d][ty + y][jl];
            const float4 Bv = *(const float4*)&tile[d][ty + y][jl + 4];
            const float v[8] = {A.x, A.y, A.z, A.w, Bv.x, Bv.y, Bv.z, Bv.w};
#pragma unroll
            for (int p = 0; p < PPT; p++) {
#pragma unroll
                for (int xk = 0; xk < 4; xk++)
                    S[p] += fminf(v[p + xk], tclip[p]);
            }
        }
    }

    float invS[PPT];
#pragma unroll
    for (int p = 0; p < PPT; p++) invS[p] = 1.0f / fmaxf(S[p], 1e-20f);

    // Pass 3: write 128 channels, 4 pixels each, as STG.128.
    // Warp covers j0 + jl + [0,128) contiguous -> 512B per warp per channel.
    float* ob = out + (size_t)b * 128 * HW + (size_t)i * W + (j0 + jl);
#pragma unroll
    for (int d = 0; d < 8; d++) {
#pragma unroll
        for (int y = 0; y < 4; y++) {
            const float4 A  = *(const float4*)&tile[d][ty + y][jl];
            const float4 Bv = *(const float4*)&tile[d][ty + y][jl + 4];
            const float v[8] = {A.x, A.y, A.z, A.w, Bv.x, Bv.y, Bv.z, Bv.w};
#pragma unroll
            for (int xk = 0; xk < 4; xk++) {
                const int c = d * 16 + y * 4 + xk;
                float4 r;
                r.x = fsqrt_fast(fmaf(fminf(v[0 + xk], tclip[0]), invS[0], 1e-10f));
                r.y = fsqrt_fast(fmaf(fminf(v[1 + xk], tclip[1]), invS[1], 1e-10f));
                r.z = fsqrt_fast(fmaf(fminf(v[2 + xk], tclip[2]), invS[2], 1e-10f));
                r.w = fsqrt_fast(fmaf(fminf(v[3 + xk], tclip[3]), invS[3], 1e-10f));
                *(float4*)&ob[(size_t)c * HW] = r;
            }
        }
    }
}

// ----------------------------------------------------------------------------
extern "C" void kernel_launch(void* const* d_in, const int* in_sizes, int n_in,
                              void* d_out, int out_size) {
    const float* x = (const float*)d_in[0];
    float* out = (float*)d_out;

    dim3 blk(32, 8);
    dim3 g1(W / 32, H / 8, B);                       // (16, 64, 2)
    dim3 g2((PW + 31) / 32, (PH + 7) / 8, B * 8);    // (17, 65, 16)
    dim3 g3(W / TILEX, H / TYV, B);                  // (4, 64, 2)

    k_ang<<<g1, blk>>>(x);
    k_pool<<<g2, blk>>>();
    k_final<<<g3, blk>>>(out);
}

// round 3
// speedup vs baseline: 1.8482x; 1.8482x over previous
#include <cuda_runtime.h>
#include <cuda_bf16.h>
#include <math.h>

// Problem constants (hardcoded for this dataset: B=2, H=W=512)
#define B   2
#define H   512
#define W   512
#define HW  (H*W)            // 262144
#define PH  (H+1)            // pooled H = 513
#define PW  (W+1)            // pooled W = 513
#define PHW (PH*PW)          // 263169

// Scratch (static device memory; allocation APIs are forbidden)
__device__ float  g_ang[(size_t)B * 8 * HW];       // (B,8,512,512)  16 MB
__device__ float  g_pooled[(size_t)B * 8 * PHW];   // (B,8,513,513)  16.8 MB
__device__ float2 g_tinv[(size_t)B * HW];          // per-pixel (t, invS), 4 MB

__device__ __forceinline__ float fsqrt_fast(float x) {
    float r;
    asm("sqrt.approx.f32 %0, %1;" : "=f"(r) : "f"(x));
    return r;
}

// ----------------------------------------------------------------------------
// K1: spatial gradient (central diff /2, replicate pad) -> mag/ori -> 8-bin
//     soft angular histogram.
// ----------------------------------------------------------------------------
__global__ __launch_bounds__(256)
void k_ang(const float* __restrict__ x) {
    const int j = blockIdx.x * 32 + threadIdx.x;
    const int i = blockIdx.y * 8  + threadIdx.y;
    const int b = blockIdx.z;

    const float* xb = x + (size_t)b * HW;
    const int jm = max(j - 1, 0),     jp = min(j + 1, W - 1);
    const int im = max(i - 1, 0),     ip = min(i + 1, H - 1);

    const float gx = 0.5f * (xb[i * W + jp] - xb[i * W + jm]);
    const float gy = 0.5f * (xb[ip * W + j] - xb[im * W + j]);

    const float mag = sqrtf(gx * gx + gy * gy + 1e-10f);
    const float TWO_PI = 6.283185307179586f;
    const float ori = atan2f(gy, gx + 1e-10f) + TWO_PI;
    const float o   = ori * (8.0f / TWO_PI);
    const float bof = floorf(o);
    const float w1  = o - bof;
    const int b0 = ((int)bof) & 7;
    const int b1 = (b0 + 1) & 7;
    const float v0 = (1.0f - w1) * mag;
    const float v1 = w1 * mag;

    float* ap = g_ang + (size_t)b * 8 * HW + (size_t)i * W + j;
#pragma unroll
    for (int d = 0; d < 8; d++) {
        float v = (d == b0) ? v0 : ((d == b1) ? v1 : 0.0f);
        ap[(size_t)d * HW] = v;
    }
}

// ----------------------------------------------------------------------------
// K2: 4x4 triangular pooling (weights [.25,.75,.75,.25]^2), pad=2, stride 1,
//     zero padding. ang(512x512) -> pooled(513x513) per (b,d).
// ----------------------------------------------------------------------------
__global__ __launch_bounds__(256)
void k_pool() {
    const int q  = blockIdx.x * 32 + threadIdx.x;   // 0..512
    const int p  = blockIdx.y * 8  + threadIdx.y;   // 0..512
    const int bd = blockIdx.z;                      // 0..15
    if (p >= PH || q >= PW) return;

    const float* a = g_ang + (size_t)bd * HW;
    const float wv[4] = {0.25f, 0.75f, 0.75f, 0.25f};

    float acc = 0.0f;
#pragma unroll
    for (int ky = 0; ky < 4; ky++) {
        const int r = p - 2 + ky;
        if (r < 0 || r >= H) continue;
        float rowacc = 0.0f;
#pragma unroll
        for (int kx = 0; kx < 4; kx++) {
            const int c = q - 2 + kx;
            if (c < 0 || c >= W) continue;
            rowacc = fmaf(wv[kx], a[(size_t)r * W + c], rowacc);
        }
        acc = fmaf(wv[ky], rowacc, acc);
    }
    g_pooled[(size_t)bd * PHW + (size_t)p * PW + q] = acc;
}

// ----------------------------------------------------------------------------
// K3a: per-pixel normalization scalars. Same SMEM tile structure as the proven
//      R1 kernel, but stops after passes 1+2 and stores only (t, invS).
//      t = 0.2*sqrt(sum v^2), S = sum min(v, t), invS = 1/max(S, tiny).
// ----------------------------------------------------------------------------
#define TX 32
#define TY 8

__global__ __launch_bounds__(256)
void k_scal() {
    __shared__ float tile[8][TY + 3][TX + 3];   // 12320 B

    const int b  = blockIdx.z;
    const int j0 = blockIdx.x * TX;
    const int i0 = blockIdx.y * TY;
    const int tx = threadIdx.x, ty = threadIdx.y;
    const int tid = ty * TX + tx;

    const float* pb = g_pooled + (size_t)b * 8 * PHW;
    const int NLOAD = 8 * (TY + 3) * (TX + 3);
    for (int idx = tid; idx < NLOAD; idx += TX * TY) {
        const int d   = idx / ((TY + 3) * (TX + 3));
        const int rem = idx % ((TY + 3) * (TX + 3));
        const int r = rem / (TX + 3);
        const int c = rem % (TX + 3);
        const int pp = i0 - 1 + r;
        const int qq = j0 - 1 + c;
        float v = 0.0f;
        if (pp >= 0 && pp < PH && qq >= 0 && qq < PW)
            v = pb[(size_t)d * PHW + (size_t)pp * PW + qq];
        tile[d][r][c] = v;
    }
    __syncthreads();

    const int i = i0 + ty;
    const int j = j0 + tx;

    float sumsq = 0.0f;
#pragma unroll
    for (int d = 0; d < 8; d++)
#pragma unroll
        for (int y = 0; y < 4; y++)
#pragma unroll
            for (int xk = 0; xk < 4; xk++) {
                const float v = tile[d][ty + y][tx + xk];
                sumsq = fmaf(v, v, sumsq);
            }

    const float t = 0.2f * sqrtf(sumsq);

    float S = 0.0f;
#pragma unroll
    for (int d = 0; d < 8; d++)
#pragma unroll
        for (int y = 0; y < 4; y++)
#pragma unroll
            for (int xk = 0; xk < 4; xk++)
                S += fminf(tile[d][ty + y][tx + xk], t);

    const float invS = 1.0f / fmaxf(S, 1e-20f);

    g_tinv[(size_t)b * HW + (size_t)i * W + j] = make_float2(t, invS);
}

// ----------------------------------------------------------------------------
// K3b: output writer. out[b,c,i,j] with c = d*16 + y*4 + x:
//      out = sqrt( min(pooled[b,d,i-1+y,j-1+x], t[i,j]) * invS[i,j] + 1e-10 )
//      Each thread: 4 consecutive j. Tiny register footprint, STG.128 stores.
// ----------------------------------------------------------------------------
__global__ __launch_bounds__(128)
void k_write(float* __restrict__ out) {
    const int i = blockIdx.x;           // 0..511
    const int c = blockIdx.y;           // 0..127
    const int b = blockIdx.z;           // 0..1
    const int j = threadIdx.x * 4;      // 0..508

    const int d  = c >> 4;
    const int y  = (c >> 2) & 3;
    const int xk = c & 3;

    const int r = i - 1 + y;
    const bool rvalid = (r >= 0) && (r < PH);
    const float* prow = g_pooled + ((size_t)(b * 8 + d) * PHW + (size_t)(rvalid ? r : 0) * PW);

    // pooled values at columns j+k+xk-1, k=0..3
    float v0 = 0.f, v1 = 0.f, v2 = 0.f, v3 = 0.f;
    const int q0 = j + xk - 1;
    if (rvalid) {
        if (q0 >= 0 && q0 + 3 < PW) {           // fast path: all 4 in range
            v0 = __ldg(prow + q0);
            v1 = __ldg(prow + q0 + 1);
            v2 = __ldg(prow + q0 + 2);
            v3 = __ldg(prow + q0 + 3);
        } else {
            if (q0 >= 0 && q0 < PW)         v0 = __ldg(prow + q0);
            if (q0 + 1 >= 0 && q0 + 1 < PW) v1 = __ldg(prow + q0 + 1);
            if (q0 + 2 >= 0 && q0 + 2 < PW) v2 = __ldg(prow + q0 + 2);
            if (q0 + 3 < PW)                v3 = __ldg(prow + q0 + 3);
        }
    }

    // (t, invS) for the 4 pixels: 32B aligned -> two LDG.128
    const float4* tv = (const float4*)(g_tinv + (size_t)b * HW + (size_t)i * W + j);
    const float4 t01 = __ldg(tv);        // t0, inv0, t1, inv1
    const float4 t23 = __ldg(tv + 1);    // t2, inv2, t3, inv3

    float4 rs;
    rs.x = fsqrt_fast(fmaf(fminf(v0, t01.x), t01.y, 1e-10f));
    rs.y = fsqrt_fast(fmaf(fminf(v1, t01.z), t01.w, 1e-10f));
    rs.z = fsqrt_fast(fmaf(fminf(v2, t23.x), t23.y, 1e-10f));
    rs.w = fsqrt_fast(fmaf(fminf(v3, t23.z), t23.w, 1e-10f));

    *(float4*)(out + ((size_t)(b * 128 + c) * HW + (size_t)i * W + j)) = rs;
}

// ----------------------------------------------------------------------------
extern "C" void kernel_launch(void* const* d_in, const int* in_sizes, int n_in,
                              void* d_out, int out_size) {
    const float* x = (const float*)d_in[0];
    float* out = (float*)d_out;

    dim3 blk(32, 8);
    dim3 g1(W / 32, H / 8, B);                       // (16, 64, 2)
    dim3 g2((PW + 31) / 32, (PH + 7) / 8, B * 8);    // (17, 65, 16)
    dim3 g3(W / TX, H / TY, B);                      // (16, 64, 2)
    dim3 g4(H, 128, B);                              // (512, 128, 2)

    k_ang<<<g1, blk>>>(x);
    k_pool<<<g2, blk>>>();
    k_scal<<<g3, blk>>>();
    k_write<<<g4, 128>>>(out);
}

// round 4
// speedup vs baseline: 2.4685x; 1.3357x over previous
#include <cuda_runtime.h>
#include <cuda_bf16.h>
#include <math.h>

// Problem constants (hardcoded: B=2, H=W=512)
#define B   2
#define H   512
#define W   512
#define HW  (H*W)            // 262144
#define PH  (H+1)            // pooled rows = 513
#define PW  (W+1)            // pooled valid cols = 513
#define PWP 516              // padded pooled row stride (cols 513..515 are zero)
#define PSZ ((size_t)PH * PWP)

// Scratch (static device memory; allocation APIs are forbidden)
__device__ float  g_ang[(size_t)B * 8 * HW];      // (B,8,512,512)  16 MB
__device__ float  g_pooled[(size_t)B * 8 * PSZ];  // (B,8,513,516)  ~17 MB
__device__ float2 g_tinv[(size_t)B * HW];         // per-pixel (t, invS), 4 MB

__device__ __forceinline__ float fsqrt_fast(float x) {
    float r;
    asm("sqrt.approx.f32 %0, %1;" : "=f"(r) : "f"(x));
    return r;
}

// ----------------------------------------------------------------------------
// K1: spatial gradient -> mag/ori -> 8-bin soft angular histogram.
// ----------------------------------------------------------------------------
__global__ __launch_bounds__(256)
void k_ang(const float* __restrict__ x) {
    const int j = blockIdx.x * 32 + threadIdx.x;
    const int i = blockIdx.y * 8  + threadIdx.y;
    const int b = blockIdx.z;

    const float* xb = x + (size_t)b * HW;
    const int jm = max(j - 1, 0),     jp = min(j + 1, W - 1);
    const int im = max(i - 1, 0),     ip = min(i + 1, H - 1);

    const float gx = 0.5f * (xb[i * W + jp] - xb[i * W + jm]);
    const float gy = 0.5f * (xb[ip * W + j] - xb[im * W + j]);

    const float mag = sqrtf(gx * gx + gy * gy + 1e-10f);
    const float TWO_PI = 6.283185307179586f;
    const float ori = atan2f(gy, gx + 1e-10f) + TWO_PI;
    const float o   = ori * (8.0f / TWO_PI);
    const float bof = floorf(o);
    const float w1  = o - bof;
    const int b0 = ((int)bof) & 7;
    const int b1 = (b0 + 1) & 7;
    const float v0 = (1.0f - w1) * mag;
    const float v1 = w1 * mag;

    float* ap = g_ang + (size_t)b * 8 * HW + (size_t)i * W + j;
#pragma unroll
    for (int d = 0; d < 8; d++) {
        float v = (d == b0) ? v0 : ((d == b1) ? v1 : 0.0f);
        ap[(size_t)d * HW] = v;
    }
}

// ----------------------------------------------------------------------------
// K2: 4x4 triangular pooling, pad=2, zero padding. 4 outputs/thread, STG.128.
//     Also zero-fills pooled padding cols [513,516).
// ----------------------------------------------------------------------------
__global__ __launch_bounds__(256)
void k_pool() {
    const int qt = blockIdx.x * 32 + threadIdx.x;   // thread column group
    const int q0 = qt * 4;                          // first output col
    const int p  = blockIdx.y * 8 + threadIdx.y;    // pooled row 0..512
    const int bd = blockIdx.z;                      // b*8+d
    if (q0 >= PWP || p >= PH) return;

    const float* a = g_ang + (size_t)bd * HW;
    const float w0 = 0.25f, w1 = 0.75f;

    float o0 = 0.f, o1 = 0.f, o2 = 0.f, o3 = 0.f;
#pragma unroll
    for (int ky = 0; ky < 4; ky++) {
        const int r = p - 2 + ky;
        if (r < 0 || r >= H) continue;
        const float* row = a + (size_t)r * W;
        float t[7];
#pragma unroll
        for (int m = 0; m < 7; m++) {
            const int c = q0 - 2 + m;
            t[m] = (c >= 0 && c < W) ? __ldg(row + c) : 0.0f;
        }
        const float wy = (ky == 0 || ky == 3) ? w0 : w1;
        o0 = fmaf(wy, fmaf(w0, t[0] + t[3], fmaf(w1, t[1] + t[2], 0.f)), o0);
        o1 = fmaf(wy, fmaf(w0, t[1] + t[4], fmaf(w1, t[2] + t[3], 0.f)), o1);
        o2 = fmaf(wy, fmaf(w0, t[2] + t[5], fmaf(w1, t[3] + t[4], 0.f)), o2);
        o3 = fmaf(wy, fmaf(w0, t[3] + t[6], fmaf(w1, t[4] + t[5], 0.f)), o3);
    }
    // zero padding cols >= PW
    if (q0 + 1 >= PW) o1 = 0.f;
    if (q0 + 2 >= PW) o2 = 0.f;
    if (q0 + 3 >= PW) o3 = 0.f;
    if (q0     >= PW) o0 = 0.f;

    *(float4*)(g_pooled + (size_t)bd * PSZ + (size_t)p * PWP + q0) =
        make_float4(o0, o1, o2, o3);
}

// ----------------------------------------------------------------------------
// K3: per-pixel normalization scalars (t, invS). Proven R1 structure.
// ----------------------------------------------------------------------------
#define TX 32
#define TY 8

__global__ __launch_bounds__(256)
void k_scal() {
    __shared__ float tile[8][TY + 3][TX + 3];   // 12320 B

    const int b  = blockIdx.z;
    const int j0 = blockIdx.x * TX;
    const int i0 = blockIdx.y * TY;
    const int tx = threadIdx.x, ty = threadIdx.y;
    const int tid = ty * TX + tx;

    const float* pb = g_pooled + (size_t)b * 8 * PSZ;
    const int NLOAD = 8 * (TY + 3) * (TX + 3);
    for (int idx = tid; idx < NLOAD; idx += TX * TY) {
        const int d   = idx / ((TY + 3) * (TX + 3));
        const int rem = idx % ((TY + 3) * (TX + 3));
        const int r = rem / (TX + 3);
        const int c = rem % (TX + 3);
        const int pp = i0 - 1 + r;
        const int qq = j0 - 1 + c;
        float v = 0.0f;
        if (pp >= 0 && pp < PH && qq >= 0 && qq < PW)
            v = pb[(size_t)d * PSZ + (size_t)pp * PWP + qq];
        tile[d][r][c] = v;
    }
    __syncthreads();

    const int i = i0 + ty;
    const int j = j0 + tx;

    float sumsq = 0.0f;
#pragma unroll
    for (int d = 0; d < 8; d++)
#pragma unroll
        for (int y = 0; y < 4; y++)
#pragma unroll
            for (int xk = 0; xk < 4; xk++) {
                const float v = tile[d][ty + y][tx + xk];
                sumsq = fmaf(v, v, sumsq);
            }

    const float t = 0.2f * sqrtf(sumsq);

    float S = 0.0f;
#pragma unroll
    for (int d = 0; d < 8; d++)
#pragma unroll
        for (int y = 0; y < 4; y++)
#pragma unroll
            for (int xk = 0; xk < 4; xk++)
                S += fminf(tile[d][ty + y][tx + xk], t);

    const float invS = 1.0f / fmaxf(S, 1e-20f);

    g_tinv[(size_t)b * HW + (size_t)i * W + j] = make_float2(t, invS);
}

// ----------------------------------------------------------------------------
// K4: output writer. One block per (b, d, i). Stage 4 pooled rows + tinv row
//     in SMEM, then emit 16 channels x 512 pixels as pure STG.128.
//     smem row layout: srow[y][c] = pooled[d, i-1+y, c-1]  (c = q+1, 0..515)
// ----------------------------------------------------------------------------
__global__ __launch_bounds__(128)
void k_write(float* __restrict__ out) {
    __shared__ float srow[4][520];       // 8320 B
    __shared__ float2 stv[512];          // 4096 B

    const int i = blockIdx.x;            // 0..511
    const int d = blockIdx.y;            // 0..7
    const int b = blockIdx.z;            // 0..1
    const int tid = threadIdx.x;         // 0..127

    // Stage pooled rows i-1 .. i+2 (invalid rows -> 0). Cols: srow[y][0] = 0
    // (q=-1); srow[y][1..516) = pooled[r][0..515] (513..515 already zero).
    const float* pbase = g_pooled + (size_t)(b * 8 + d) * PSZ;
#pragma unroll
    for (int y = 0; y < 4; y++) {
        const int r = i - 1 + y;
        const bool rv = (r >= 0) && (r < PH);
        const float4* src = (const float4*)(pbase + (size_t)(rv ? r : 0) * PWP);
        // 516 floats = 129 float4; 128 threads -> one each + thread 0 does last
        {
            float4 v = rv ? __ldg(src + tid) : make_float4(0.f, 0.f, 0.f, 0.f);
            const int c = tid * 4 + 1;
            srow[y][c] = v.x; srow[y][c + 1] = v.y;
            srow[y][c + 2] = v.z; srow[y][c + 3] = v.w;
        }
        if (tid == 0) {
            float4 v = rv ? __ldg(src + 128) : make_float4(0.f, 0.f, 0.f, 0.f);
            srow[y][513] = v.x; srow[y][514] = v.y; srow[y][515] = v.z;
            srow[y][0] = 0.0f;
        }
    }
    // Stage tinv row: 512 float2 = 256 float4
    {
        const float4* tsrc = (const float4*)(g_tinv + (size_t)b * HW + (size_t)i * W);
        float4* tdst = (float4*)stv;
        tdst[tid]       = __ldg(tsrc + tid);
        tdst[tid + 128] = __ldg(tsrc + tid + 128);
    }
    __syncthreads();

    const int jl = tid * 4;              // pixels jl..jl+3
    const float2 p0 = stv[jl],     p1 = stv[jl + 1];
    const float2 p2 = stv[jl + 2], p3 = stv[jl + 3];

    float* ob = out + ((size_t)(b * 128 + d * 16) * HW + (size_t)i * W + jl);

#pragma unroll
    for (int y = 0; y < 4; y++) {
        // channel xk at pixel jl+k reads srow[y][jl + k + xk]
        const float4 A  = *(const float4*)&srow[y][jl];
        const float4 Bv = *(const float4*)&srow[y][jl + 4];
        const float a0 = A.x,  a1 = A.y,  a2 = A.z,  a3 = A.w;
        const float a4 = Bv.x, a5 = Bv.y, a6 = Bv.z;
#pragma unroll
        for (int xk = 0; xk < 4; xk++) {
            float v0, v1, v2, v3;
            if (xk == 0)      { v0 = a0; v1 = a1; v2 = a2; v3 = a3; }
            else if (xk == 1) { v0 = a1; v1 = a2; v2 = a3; v3 = a4; }
            else if (xk == 2) { v0 = a2; v1 = a3; v2 = a4; v3 = a5; }
            else              { v0 = a3; v1 = a4; v2 = a5; v3 = a6; }
            float4 rs;
            rs.x = fsqrt_fast(fmaf(fminf(v0, p0.x), p0.y, 1e-10f));
            rs.y = fsqrt_fast(fmaf(fminf(v1, p1.x), p1.y, 1e-10f));
            rs.z = fsqrt_fast(fmaf(fminf(v2, p2.x), p2.y, 1e-10f));
            rs.w = fsqrt_fast(fmaf(fminf(v3, p3.x), p3.y, 1e-10f));
            *(float4*)&ob[(size_t)(y * 4 + xk) * HW] = rs;
        }
    }
}

// ----------------------------------------------------------------------------
extern "C" void kernel_launch(void* const* d_in, const int* in_sizes, int n_in,
                              void* d_out, int out_size) {
    const float* x = (const float*)d_in[0];
    float* out = (float*)d_out;

    dim3 blk(32, 8);
    dim3 g1(W / 32, H / 8, B);                        // (16, 64, 2)
    dim3 g2((PWP / 4 + 31) / 32, (PH + 7) / 8, B * 8);// (5, 65, 16)
    dim3 g3(W / TX, H / TY, B);                       // (16, 64, 2)
    dim3 g4(H, 8, B);                                 // (512, 8, 2)

    k_ang<<<g1, blk>>>(x);
    k_pool<<<g2, blk>>>();
    k_scal<<<g3, blk>>>();
    k_write<<<g4, 128>>>(out);
}

// round 5
// speedup vs baseline: 2.6095x; 1.0571x over previous
#include <cuda_runtime.h>
#include <cuda_bf16.h>
#include <math.h>

// Problem constants (hardcoded: B=2, H=W=512)
#define B   2
#define H   512
#define W   512
#define HW  (H*W)            // 262144
#define PH  (H+1)            // pooled rows = 513
#define PW  (W+1)            // pooled valid cols = 513
#define PWP 516              // padded pooled row stride (cols 513..515 are zero)
#define PSZ ((size_t)PH * PWP)

// Scratch (static device memory; allocation APIs are forbidden)
__device__ float  g_ang[(size_t)B * 8 * HW];      // (B,8,512,512)  16 MB
__device__ float  g_pooled[(size_t)B * 8 * PSZ];  // (B,8,513,516)  ~17 MB
__device__ float2 g_tinv[(size_t)B * HW];         // per-pixel (t, invS), 4 MB

__device__ __forceinline__ float fsqrt_fast(float x) {
    float r;
    asm("sqrt.approx.f32 %0, %1;" : "=f"(r) : "f"(x));
    return r;
}

// ----------------------------------------------------------------------------
// K1: spatial gradient -> mag/ori -> 8-bin soft angular histogram.
// ----------------------------------------------------------------------------
__global__ __launch_bounds__(256)
void k_ang(const float* __restrict__ x) {
    const int j = blockIdx.x * 32 + threadIdx.x;
    const int i = blockIdx.y * 8  + threadIdx.y;
    const int b = blockIdx.z;

    const float* xb = x + (size_t)b * HW;
    const int jm = max(j - 1, 0),     jp = min(j + 1, W - 1);
    const int im = max(i - 1, 0),     ip = min(i + 1, H - 1);

    const float gx = 0.5f * (xb[i * W + jp] - xb[i * W + jm]);
    const float gy = 0.5f * (xb[ip * W + j] - xb[im * W + j]);

    const float mag = sqrtf(gx * gx + gy * gy + 1e-10f);
    const float TWO_PI = 6.283185307179586f;
    const float ori = atan2f(gy, gx + 1e-10f) + TWO_PI;
    const float o   = ori * (8.0f / TWO_PI);
    const float bof = floorf(o);
    const float w1  = o - bof;
    const int b0 = ((int)bof) & 7;
    const int b1 = (b0 + 1) & 7;
    const float v0 = (1.0f - w1) * mag;
    const float v1 = w1 * mag;

    float* ap = g_ang + (size_t)b * 8 * HW + (size_t)i * W + j;
#pragma unroll
    for (int d = 0; d < 8; d++) {
        float v = (d == b0) ? v0 : ((d == b1) ? v1 : 0.0f);
        ap[(size_t)d * HW] = v;
    }
}

// ----------------------------------------------------------------------------
// K2: 4x4 triangular pooling, separable. One block per (bd, pooled-row p).
//     Vertical combine (4 rows, coalesced LDG.128) -> SMEM line,
//     horizontal combine (2 aligned LDS.128) -> STG.128.
//     svc[c+2] = sum_ky wy[ky]*ang[p-2+ky][c]; zeros at both edges.
//     pooled[p][q] = .25*(svc[q]+svc[q+3]) + .75*(svc[q+1]+svc[q+2])
// ----------------------------------------------------------------------------
__global__ __launch_bounds__(128)
void k_pool() {
    __shared__ __align__(16) float svc[520];

    const int p  = blockIdx.x;      // 0..512
    const int bd = blockIdx.y;      // 0..15
    const int t  = threadIdx.x;     // 0..127

    const float* a = g_ang + (size_t)bd * HW;

    float4 acc = make_float4(0.f, 0.f, 0.f, 0.f);
#pragma unroll
    for (int ky = 0; ky < 4; ky++) {
        const int r = p - 2 + ky;
        if (r < 0 || r >= H) continue;
        const float wy = (ky == 0 || ky == 3) ? 0.25f : 0.75f;
        const float4 v = __ldg((const float4*)(a + (size_t)r * W) + t);
        acc.x = fmaf(wy, v.x, acc.x);
        acc.y = fmaf(wy, v.y, acc.y);
        acc.z = fmaf(wy, v.z, acc.z);
        acc.w = fmaf(wy, v.w, acc.w);
    }
    svc[4 * t + 2] = acc.x;
    svc[4 * t + 3] = acc.y;
    svc[4 * t + 4] = acc.z;
    svc[4 * t + 5] = acc.w;
    if (t < 2) svc[t] = 0.0f;            // cols -2,-1
    if (t < 6) svc[514 + t] = 0.0f;      // cols 512..517 (vcomb beyond W)
    __syncthreads();

    const int q0 = 4 * t;
    const float4 A  = *(const float4*)&svc[q0];
    const float4 Bv = *(const float4*)&svc[q0 + 4];
    const float s0 = A.x,  s1 = A.y,  s2 = A.z, s3 = A.w;
    const float s4 = Bv.x, s5 = Bv.y, s6 = Bv.z;

    float4 o;
    o.x = 0.25f * (s0 + s3) + 0.75f * (s1 + s2);
    o.y = 0.25f * (s1 + s4) + 0.75f * (s2 + s3);
    o.z = 0.25f * (s2 + s5) + 0.75f * (s3 + s4);
    o.w = 0.25f * (s3 + s6) + 0.75f * (s4 + s5);

    float* prow = g_pooled + (size_t)bd * PSZ + (size_t)p * PWP;
    *(float4*)(prow + q0) = o;

    if (t == 0) {
        // q = 512 valid; 513..515 are zero padding
        const float z = 0.25f * (svc[512] + svc[515]) + 0.75f * (svc[513] + svc[514]);
        *(float4*)(prow + 512) = make_float4(z, 0.f, 0.f, 0.f);
    }
}

// ----------------------------------------------------------------------------
// K3: per-pixel normalization scalars (t, invS). Warp-per-channel tile load
//     (division-free), then the proven two LDS passes.
// ----------------------------------------------------------------------------
#define TX 32
#define TY 8

__global__ __launch_bounds__(256)
void k_scal() {
    __shared__ float tile[8][TY + 3][TX + 3];   // 12320 B

    const int b  = blockIdx.z;
    const int j0 = blockIdx.x * TX;
    const int i0 = blockIdx.y * TY;
    const int tx = threadIdx.x, ty = threadIdx.y;

    // Warp w loads channel d=w: rows i0-1..i0+9, cols j0-1..j0+33.
    // Pooled padding cols (>=513) are zero in memory, so only qq>=0 and
    // row-validity need predication.
    {
        const int lane = tx;              // 0..31
        const int d    = ty;              // warp index == channel
        const float* pd = g_pooled + ((size_t)b * 8 + d) * PSZ;
#pragma unroll
        for (int r = 0; r < TY + 3; r++) {
            const int pp = i0 - 1 + r;
            const bool pv = (pp >= 0) && (pp < PH);
            const float* prow = pd + (size_t)(pv ? pp : 0) * PWP;
            {
                const int qq = j0 - 1 + lane;
                float v = 0.0f;
                if (pv && qq >= 0) v = __ldg(prow + qq);
                tile[d][r][lane] = v;
            }
            if (lane < 3) {
                const int qq = j0 + 31 + lane;   // <= 513 < PWP, padded zero
                float v = 0.0f;
                if (pv) v = __ldg(prow + qq);
                tile[d][r][32 + lane] = v;
            }
        }
    }
    __syncthreads();

    const int i = i0 + ty;
    const int j = j0 + tx;

    float sumsq = 0.0f;
#pragma unroll
    for (int d = 0; d < 8; d++)
#pragma unroll
        for (int y = 0; y < 4; y++)
#pragma unroll
            for (int xk = 0; xk < 4; xk++) {
                const float v = tile[d][ty + y][tx + xk];
                sumsq = fmaf(v, v, sumsq);
            }

    const float t = 0.2f * sqrtf(sumsq);

    float S = 0.0f;
#pragma unroll
    for (int d = 0; d < 8; d++)
#pragma unroll
        for (int y = 0; y < 4; y++)
#pragma unroll
            for (int xk = 0; xk < 4; xk++)
                S += fminf(tile[d][ty + y][tx + xk], t);

    const float invS = 1.0f / fmaxf(S, 1e-20f);

    g_tinv[(size_t)b * HW + (size_t)i * W + j] = make_float2(t, invS);
}

// ----------------------------------------------------------------------------
// K4: output writer. One block per (b, d, i). Stage 4 pooled rows + tinv row
//     in SMEM, then emit 16 channels x 512 pixels as pure STG.128.
// ----------------------------------------------------------------------------
__global__ __launch_bounds__(128)
void k_write(float* __restrict__ out) {
    __shared__ float srow[4][520];       // 8320 B
    __shared__ float2 stv[512];          // 4096 B

    const int i = blockIdx.x;            // 0..511
    const int d = blockIdx.y;            // 0..7
    const int b = blockIdx.z;            // 0..1
    const int tid = threadIdx.x;         // 0..127

    const float* pbase = g_pooled + (size_t)(b * 8 + d) * PSZ;
#pragma unroll
    for (int y = 0; y < 4; y++) {
        const int r = i - 1 + y;
        const bool rv = (r >= 0) && (r < PH);
        const float4* src = (const float4*)(pbase + (size_t)(rv ? r : 0) * PWP);
        {
            float4 v = rv ? __ldg(src + tid) : make_float4(0.f, 0.f, 0.f, 0.f);
            const int c = tid * 4 + 1;
            srow[y][c] = v.x; srow[y][c + 1] = v.y;
            srow[y][c + 2] = v.z; srow[y][c + 3] = v.w;
        }
        if (tid == 0) {
            float4 v = rv ? __ldg(src + 128) : make_float4(0.f, 0.f, 0.f, 0.f);
            srow[y][513] = v.x; srow[y][514] = v.y; srow[y][515] = v.z;
            srow[y][0] = 0.0f;
        }
    }
    {
        const float4* tsrc = (const float4*)(g_tinv + (size_t)b * HW + (size_t)i * W);
        float4* tdst = (float4*)stv;
        tdst[tid]       = __ldg(tsrc + tid);
        tdst[tid + 128] = __ldg(tsrc + tid + 128);
    }
    __syncthreads();

    const int jl = tid * 4;
    const float2 p0 = stv[jl],     p1 = stv[jl + 1];
    const float2 p2 = stv[jl + 2], p3 = stv[jl + 3];

    float* ob = out + ((size_t)(b * 128 + d * 16) * HW + (size_t)i * W + jl);

#pragma unroll
    for (int y = 0; y < 4; y++) {
        const float4 A  = *(const float4*)&srow[y][jl];
        const float4 Bv = *(const float4*)&srow[y][jl + 4];
        const float a0 = A.x,  a1 = A.y,  a2 = A.z,  a3 = A.w;
        const float a4 = Bv.x, a5 = Bv.y, a6 = Bv.z;
#pragma unroll
        for (int xk = 0; xk < 4; xk++) {
            float v0, v1, v2, v3;
            if (xk == 0)      { v0 = a0; v1 = a1; v2 = a2; v3 = a3; }
            else if (xk == 1) { v0 = a1; v1 = a2; v2 = a3; v3 = a4; }
            else if (xk == 2) { v0 = a2; v1 = a3; v2 = a4; v3 = a5; }
            else              { v0 = a3; v1 = a4; v2 = a5; v3 = a6; }
            float4 rs;
            rs.x = fsqrt_fast(fmaf(fminf(v0, p0.x), p0.y, 1e-10f));
            rs.y = fsqrt_fast(fmaf(fminf(v1, p1.x), p1.y, 1e-10f));
            rs.z = fsqrt_fast(fmaf(fminf(v2, p2.x), p2.y, 1e-10f));
            rs.w = fsqrt_fast(fmaf(fminf(v3, p3.x), p3.y, 1e-10f));
            *(float4*)&ob[(size_t)(y * 4 + xk) * HW] = rs;
        }
    }
}

// ----------------------------------------------------------------------------
extern "C" void kernel_launch(void* const* d_in, const int* in_sizes, int n_in,
                              void* d_out, int out_size) {
    const float* x = (const float*)d_in[0];
    float* out = (float*)d_out;

    dim3 blk(32, 8);
    dim3 g1(W / 32, H / 8, B);                       // (16, 64, 2)
    dim3 g2(PH, B * 8);                              // (513, 16)
    dim3 g3(W / TX, H / TY, B);                      // (16, 64, 2)
    dim3 g4(H, 8, B);                                // (512, 8, 2)

    k_ang<<<g1, blk>>>(x);
    k_pool<<<g2, 128>>>();
    k_scal<<<g3, blk>>>();
    k_write<<<g4, 128>>>(out);
}

// round 6
// speedup vs baseline: 4.5344x; 1.7376x over previous
#include <cuda_runtime.h>
#include <cuda_bf16.h>
#include <math.h>

// Problem constants (hardcoded: B=2, H=W=512)
#define B   2
#define H   512
#define W   512
#define HW  (H*W)            // 262144
#define PH  (H+1)            // pooled rows = 513
#define PW  (W+1)            // pooled valid cols = 513
#define PWP 516              // padded pooled row stride (cols 513..515 are zero)
#define PSZ ((size_t)PH * PWP)

// Scratch (static device memory; allocation APIs are forbidden)
__device__ float  g_ang[(size_t)B * 8 * HW];      // (B,8,512,512)  16 MB
__device__ float  g_pooled[(size_t)B * 8 * PSZ];  // (B,8,513,516)  ~17 MB
__device__ float2 g_tinv[(size_t)B * HW];         // per-pixel (t, invS), 4 MB

__device__ __forceinline__ float fsqrt_fast(float x) {
    float r;
    asm("sqrt.approx.f32 %0, %1;" : "=f"(r) : "f"(x));
    return r;
}

// ----------------------------------------------------------------------------
// K1: spatial gradient -> mag/ori -> 8-bin soft angular histogram.
// ----------------------------------------------------------------------------
__global__ __launch_bounds__(256)
void k_ang(const float* __restrict__ x) {
    const int j = blockIdx.x * 32 + threadIdx.x;
    const int i = blockIdx.y * 8  + threadIdx.y;
    const int b = blockIdx.z;

    const float* xb = x + (size_t)b * HW;
    const int jm = max(j - 1, 0),     jp = min(j + 1, W - 1);
    const int im = max(i - 1, 0),     ip = min(i + 1, H - 1);

    const float gx = 0.5f * (xb[i * W + jp] - xb[i * W + jm]);
    const float gy = 0.5f * (xb[ip * W + j] - xb[im * W + j]);

    const float mag = sqrtf(gx * gx + gy * gy + 1e-10f);
    const float TWO_PI = 6.283185307179586f;
    const float ori = atan2f(gy, gx + 1e-10f) + TWO_PI;
    const float o   = ori * (8.0f / TWO_PI);
    const float bof = floorf(o);
    const float w1  = o - bof;
    const int b0 = ((int)bof) & 7;
    const int b1 = (b0 + 1) & 7;
    const float v0 = (1.0f - w1) * mag;
    const float v1 = w1 * mag;

    float* ap = g_ang + (size_t)b * 8 * HW + (size_t)i * W + j;
#pragma unroll
    for (int d = 0; d < 8; d++) {
        float v = (d == b0) ? v0 : ((d == b1) ? v1 : 0.0f);
        ap[(size_t)d * HW] = v;
    }
}

// ----------------------------------------------------------------------------
// K2: 4x4 triangular pooling, separable. One block per (bd, pooled-row p).
// ----------------------------------------------------------------------------
__global__ __launch_bounds__(128)
void k_pool() {
    __shared__ __align__(16) float svc[520];

    const int p  = blockIdx.x;      // 0..512
    const int bd = blockIdx.y;      // 0..15
    const int t  = threadIdx.x;     // 0..127

    const float* a = g_ang + (size_t)bd * HW;

    float4 acc = make_float4(0.f, 0.f, 0.f, 0.f);
#pragma unroll
    for (int ky = 0; ky < 4; ky++) {
        const int r = p - 2 + ky;
        if (r < 0 || r >= H) continue;
        const float wy = (ky == 0 || ky == 3) ? 0.25f : 0.75f;
        const float4 v = __ldg((const float4*)(a + (size_t)r * W) + t);
        acc.x = fmaf(wy, v.x, acc.x);
        acc.y = fmaf(wy, v.y, acc.y);
        acc.z = fmaf(wy, v.z, acc.z);
        acc.w = fmaf(wy, v.w, acc.w);
    }
    svc[4 * t + 2] = acc.x;
    svc[4 * t + 3] = acc.y;
    svc[4 * t + 4] = acc.z;
    svc[4 * t + 5] = acc.w;
    if (t < 2) svc[t] = 0.0f;
    if (t < 6) svc[514 + t] = 0.0f;
    __syncthreads();

    const int q0 = 4 * t;
    const float4 A  = *(const float4*)&svc[q0];
    const float4 Bv = *(const float4*)&svc[q0 + 4];
    const float s0 = A.x,  s1 = A.y,  s2 = A.z, s3 = A.w;
    const float s4 = Bv.x, s5 = Bv.y, s6 = Bv.z;

    float4 o;
    o.x = 0.25f * (s0 + s3) + 0.75f * (s1 + s2);
    o.y = 0.25f * (s1 + s4) + 0.75f * (s2 + s3);
    o.z = 0.25f * (s2 + s5) + 0.75f * (s3 + s4);
    o.w = 0.25f * (s3 + s6) + 0.75f * (s4 + s5);

    float* prow = g_pooled + (size_t)bd * PSZ + (size_t)p * PWP;
    *(float4*)(prow + q0) = o;

    if (t == 0) {
        const float z = 0.25f * (svc[512] + svc[515]) + 0.75f * (svc[513] + svc[514]);
        *(float4*)(prow + 512) = make_float4(z, 0.f, 0.f, 0.f);
    }
}

// ----------------------------------------------------------------------------
// K3: per-pixel normalization scalars (t, invS). 4 pixels/thread; all tile
//     reads are aligned LDS.128 (2 per (d,y) serve 4 pixels x 4 taps).
//     tile[d][r][c] = pooled[b,d, i0-1+r, j0-1+c], row stride 132 (16B mult).
// ----------------------------------------------------------------------------
#define TXS 32                  // threads in x
#define TYS 8                   // threads in y
#define SPX 4                   // pixels per thread
#define STILEX (TXS * SPX)      // 128 pixels per block in x
#define SROWS (TYS + 3)         // 11
#define SCOLS 132               // 131 valid + 1 pad (16B-aligned rows)

__global__ __launch_bounds__(256)
void k_scal() {
    __shared__ __align__(16) float tile[8][SROWS][SCOLS];   // 46464 B

    const int b  = blockIdx.z;
    const int j0 = blockIdx.x * STILEX;
    const int i0 = blockIdx.y * TYS;
    const int tx = threadIdx.x, ty = threadIdx.y;

    // Loader: warp ty owns channel d=ty; lanes sweep 132 cols x 11 rows.
    {
        const int lane = tx;
        const int d    = ty;
        const float* pd = g_pooled + ((size_t)b * 8 + d) * PSZ;
#pragma unroll
        for (int r = 0; r < SROWS; r++) {
            const int pp = i0 - 1 + r;
            const bool pv = (pp >= 0) && (pp < PH);
            const float* prow = pd + (size_t)(pv ? pp : 0) * PWP;
#pragma unroll
            for (int cb = 0; cb < 5; cb++) {
                const int c = cb * 32 + lane;
                if (c < SCOLS) {
                    const int qq = j0 - 1 + c;     // max 514 < 516, padded zero
                    float v = 0.0f;
                    if (pv && qq >= 0) v = __ldg(prow + qq);
                    tile[d][r][c] = v;
                }
            }
        }
    }
    __syncthreads();

    const int jl = tx * SPX;         // local pixel base; tile col jl+p+xk
    const int i  = i0 + ty;

    // Pass 1: per-pixel sum of squares
    float sq0 = 0.f, sq1 = 0.f, sq2 = 0.f, sq3 = 0.f;
    for (int d = 0; d < 8; d++) {
#pragma unroll
        for (int y = 0; y < 4; y++) {
            const float4 A  = *(const float4*)&tile[d][ty + y][jl];
            const float4 Bv = *(const float4*)&tile[d][ty + y][jl + 4];
            const float a0 = A.x,  a1 = A.y,  a2 = A.z,  a3 = A.w;
            const float a4 = Bv.x, a5 = Bv.y, a6 = Bv.z;
            sq0 = fmaf(a0, a0, sq0); sq0 = fmaf(a1, a1, sq0);
            sq0 = fmaf(a2, a2, sq0); sq0 = fmaf(a3, a3, sq0);
            sq1 = fmaf(a1, a1, sq1); sq1 = fmaf(a2, a2, sq1);
            sq1 = fmaf(a3, a3, sq1); sq1 = fmaf(a4, a4, sq1);
            sq2 = fmaf(a2, a2, sq2); sq2 = fmaf(a3, a3, sq2);
            sq2 = fmaf(a4, a4, sq2); sq2 = fmaf(a5, a5, sq2);
            sq3 = fmaf(a3, a3, sq3); sq3 = fmaf(a4, a4, sq3);
            sq3 = fmaf(a5, a5, sq3); sq3 = fmaf(a6, a6, sq3);
        }
    }
    const float t0 = 0.2f * sqrtf(sq0);
    const float t1 = 0.2f * sqrtf(sq1);
    const float t2 = 0.2f * sqrtf(sq2);
    const float t3 = 0.2f * sqrtf(sq3);

    // Pass 2: per-pixel clipped L1 sum
    float S0 = 0.f, S1 = 0.f, S2 = 0.f, S3 = 0.f;
    for (int d = 0; d < 8; d++) {
#pragma unroll
        for (int y = 0; y < 4; y++) {
            const float4 A  = *(const float4*)&tile[d][ty + y][jl];
            const float4 Bv = *(const float4*)&tile[d][ty + y][jl + 4];
            const float a0 = A.x,  a1 = A.y,  a2 = A.z,  a3 = A.w;
            const float a4 = Bv.x, a5 = Bv.y, a6 = Bv.z;
            S0 += fminf(a0, t0) + fminf(a1, t0) + fminf(a2, t0) + fminf(a3, t0);
            S1 += fminf(a1, t1) + fminf(a2, t1) + fminf(a3, t1) + fminf(a4, t1);
            S2 += fminf(a2, t2) + fminf(a3, t2) + fminf(a4, t2) + fminf(a5, t2);
            S3 += fminf(a3, t3) + fminf(a4, t3) + fminf(a5, t3) + fminf(a6, t3);
        }
    }

    float2* tp = g_tinv + (size_t)b * HW + (size_t)i * W + (j0 + jl);
    *(float4*)(tp)     = make_float4(t0, 1.0f / fmaxf(S0, 1e-20f),
                                     t1, 1.0f / fmaxf(S1, 1e-20f));
    *(float4*)(tp + 2) = make_float4(t2, 1.0f / fmaxf(S2, 1e-20f),
                                     t3, 1.0f / fmaxf(S3, 1e-20f));
}

// ----------------------------------------------------------------------------
// K4: output writer. One block per (b, d, i). Stage 4 pooled rows + tinv row
//     in SMEM, then emit 16 channels x 512 pixels as streaming STG.128 (.cs).
// ----------------------------------------------------------------------------
__global__ __launch_bounds__(128)
void k_write(float* __restrict__ out) {
    __shared__ float srow[4][520];
    __shared__ float2 stv[512];

    const int i = blockIdx.x;
    const int d = blockIdx.y;
    const int b = blockIdx.z;
    const int tid = threadIdx.x;

    const float* pbase = g_pooled + (size_t)(b * 8 + d) * PSZ;
#pragma unroll
    for (int y = 0; y < 4; y++) {
        const int r = i - 1 + y;
        const bool rv = (r >= 0) && (r < PH);
        const float4* src = (const float4*)(pbase + (size_t)(rv ? r : 0) * PWP);
        {
            float4 v = rv ? __ldg(src + tid) : make_float4(0.f, 0.f, 0.f, 0.f);
            const int c = tid * 4 + 1;
            srow[y][c] = v.x; srow[y][c + 1] = v.y;
            srow[y][c + 2] = v.z; srow[y][c + 3] = v.w;
        }
        if (tid == 0) {
            float4 v = rv ? __ldg(src + 128) : make_float4(0.f, 0.f, 0.f, 0.f);
            srow[y][513] = v.x; srow[y][514] = v.y; srow[y][515] = v.z;
            srow[y][0] = 0.0f;
        }
    }
    {
        const float4* tsrc = (const float4*)(g_tinv + (size_t)b * HW + (size_t)i * W);
        float4* tdst = (float4*)stv;
        tdst[tid]       = __ldg(tsrc + tid);
        tdst[tid + 128] = __ldg(tsrc + tid + 128);
    }
    __syncthreads();

    const int jl = tid * 4;
    const float2 p0 = stv[jl],     p1 = stv[jl + 1];
    const float2 p2 = stv[jl + 2], p3 = stv[jl + 3];

    float* ob = out + ((size_t)(b * 128 + d * 16) * HW + (size_t)i * W + jl);

#pragma unroll
    for (int y = 0; y < 4; y++) {
        const float4 A  = *(const float4*)&srow[y][jl];
        const float4 Bv = *(const float4*)&srow[y][jl + 4];
        const float a0 = A.x,  a1 = A.y,  a2 = A.z,  a3 = A.w;
        const float a4 = Bv.x, a5 = Bv.y, a6 = Bv.z;
#pragma unroll
        for (int xk = 0; xk < 4; xk++) {
            float v0, v1, v2, v3;
            if (xk == 0)      { v0 = a0; v1 = a1; v2 = a2; v3 = a3; }
            else if (xk == 1) { v0 = a1; v1 = a2; v2 = a3; v3 = a4; }
            else if (xk == 2) { v0 = a2; v1 = a3; v2 = a4; v3 = a5; }
            else              { v0 = a3; v1 = a4; v2 = a5; v3 = a6; }
            float4 rs;
            rs.x = fsqrt_fast(fmaf(fminf(v0, p0.x), p0.y, 1e-10f));
            rs.y = fsqrt_fast(fmaf(fminf(v1, p1.x), p1.y, 1e-10f));
            rs.z = fsqrt_fast(fmaf(fminf(v2, p2.x), p2.y, 1e-10f));
            rs.w = fsqrt_fast(fmaf(fminf(v3, p3.x), p3.y, 1e-10f));
            __stcs((float4*)&ob[(size_t)(y * 4 + xk) * HW], rs);
        }
    }
}

// ----------------------------------------------------------------------------
extern "C" void kernel_launch(void* const* d_in, const int* in_sizes, int n_in,
                              void* d_out, int out_size) {
    const float* x = (const float*)d_in[0];
    float* out = (float*)d_out;

    dim3 blk(32, 8);
    dim3 g1(W / 32, H / 8, B);                       // (16, 64, 2)
    dim3 g2(PH, B * 8);                              // (513, 16)
    dim3 g3(W / STILEX, H / TYS, B);                 // (4, 64, 2)
    dim3 g4(H, 8, B);                                // (512, 8, 2)

    k_ang<<<g1, blk>>>(x);
    k_pool<<<g2, 128>>>();
    k_scal<<<g3, blk>>>();
    k_write<<<g4, 128>>>(out);
}